// round 10
// baseline (speedup 1.0000x reference)
#include <cuda_runtime.h>
#include <cuda_fp16.h>
#include <cstdint>

// Scratch (device globals; no runtime allocation).
__device__ __align__(16) __half g_xh[32768u * 512u]; // x as fp16
__device__ __align__(16) __half g_wh[1536u * 512u];  // Wq|Wk|Wv as fp16 (row = out col)

__device__ __forceinline__ uint32_t pack2(float a, float b) {
    __half2 h = __halves2half2(__float2half_rn(a), __float2half_rn(b));
    return *(uint32_t*)&h;
}

__device__ __forceinline__ void mma_f16(float c[4], const uint32_t a[4],
                                        uint32_t b0, uint32_t b1) {
    asm volatile(
        "mma.sync.aligned.m16n8k16.row.col.f32.f16.f16.f32 "
        "{%0,%1,%2,%3}, {%4,%5,%6,%7}, {%8,%9}, {%0,%1,%2,%3};"
        : "+f"(c[0]), "+f"(c[1]), "+f"(c[2]), "+f"(c[3])
        : "r"(a[0]), "r"(a[1]), "r"(a[2]), "r"(a[3]), "r"(b0), "r"(b1));
}

__device__ __forceinline__ void ldm_x4(uint32_t* r, uint32_t addr) {
    asm volatile("ldmatrix.sync.aligned.m8n8.x4.shared.b16 {%0,%1,%2,%3}, [%4];"
                 : "=r"(r[0]), "=r"(r[1]), "=r"(r[2]), "=r"(r[3]) : "r"(addr));
}
__device__ __forceinline__ void ldm_x4_trans(uint32_t* r, uint32_t addr) {
    asm volatile("ldmatrix.sync.aligned.m8n8.x4.trans.shared.b16 {%0,%1,%2,%3}, [%4];"
                 : "=r"(r[0]), "=r"(r[1]), "=r"(r[2]), "=r"(r[3]) : "r"(addr));
}

__device__ __forceinline__ void cp_async16(uint32_t smem_addr, const void* gptr) {
    asm volatile("cp.async.cg.shared.global [%0], [%1], 16;\n" :: "r"(smem_addr), "l"(gptr));
}
__device__ __forceinline__ void cp_commit() { asm volatile("cp.async.commit_group;"); }
template <int N> __device__ __forceinline__ void cp_wait() {
    asm volatile("cp.async.wait_group %0;" :: "n"(N));
}

// ---------------------------------------------------------------------------
// Pre-convert: fp32 -> fp16(RN). 8 floats per thread.
// ---------------------------------------------------------------------------
__global__ void __launch_bounds__(256) conv_x_kernel(const float* __restrict__ x)
{
    const int i = blockIdx.x * 256 + threadIdx.x;
    float4 v0 = ((const float4*)x)[2 * i];
    float4 v1 = ((const float4*)x)[2 * i + 1];
    uint4 u;
    u.x = pack2(v0.x, v0.y); u.y = pack2(v0.z, v0.w);
    u.z = pack2(v1.x, v1.y); u.w = pack2(v1.z, v1.w);
    ((uint4*)g_xh)[i] = u;
}

__global__ void __launch_bounds__(256) conv_w_kernel(
    const float* __restrict__ Wq, const float* __restrict__ Wk, const float* __restrict__ Wv)
{
    const int i = blockIdx.x * 256 + threadIdx.x;
    const int which = i >> 15;
    const int sub = i & 32767;
    const float* W = (which == 0) ? Wq : (which == 1) ? Wk : Wv;
    float4 v0 = ((const float4*)W)[2 * sub];
    float4 v1 = ((const float4*)W)[2 * sub + 1];
    uint4 u;
    u.x = pack2(v0.x, v0.y); u.y = pack2(v0.z, v0.w);
    u.z = pack2(v1.x, v1.y); u.w = pack2(v1.z, v1.w);
    ((uint4*)g_wh)[i] = u;
}

// ---------------------------------------------------------------------------
// Fused kernel: CTA = one (batch, window) = 64 tokens. 512 CTAs x 256 threads.
// Phase 1a: K,V = x @ W^T + b  (8 N-tiles of 128) -> smem kv_s[2][8][64][72].
// Per head-pair hp: Q tile (128 cols) -> q_s[2][64][72]; then attention for
// heads 2hp, 2hp+1 (4 warps each), output written straight to gmem fp32.
// ---------------------------------------------------------------------------
#define PW 20                        // staged-row pitch (words): 16 data + 4 pad
#define APITCH 36                    // qkv row pitch (words): 32 data + 4 pad
#define ASTG_W (64 * PW)             // 1280
#define BSTG_W (128 * PW)            // 2560
#define KV_OFF   0                   // 16 slots x 64 x 36 = 36864 words
#define Q_OFF    36864               // 2 x 64 x 36 = 4608
#define STG_OFF  41472               // 3 x 3840 = 11520
#define BIAS_OFF 52992               // 1536 words (float)
#define FUSED_SMEM (54528 * 4)       // 218112 B

__global__ void __launch_bounds__(256) fused_kernel(
    const float* __restrict__ bq, const float* __restrict__ bk, const float* __restrict__ bv,
    const float* __restrict__ Bbias, float* __restrict__ out)
{
    extern __shared__ uint32_t sm[];
    float* bias_s = (float*)(sm + BIAS_OFF);

    const int tid  = threadIdx.x;
    const int warp = tid >> 5, lane = tid & 31;
    const int g = lane >> 2, tig = lane & 3;
    const int l8 = lane >> 3, r8 = lane & 7;
    const int bw = blockIdx.x;

    const uint32_t smem_base = (uint32_t)__cvta_generic_to_shared(sm);

    // bias: concat [bq|bk|bv]
    bias_s[tid]        = bq[tid & 255];          // placeholder overwritten below
#pragma unroll
    for (int i = tid; i < 512; i += 256) {
        bias_s[i]        = bq[i];
        bias_s[512 + i]  = bk[i];
        bias_s[1024 + i] = bv[i];
    }

    // GEMM warp layout: 16x64 warp tiles, 4 M-groups x 2 N-groups.
    const int wm = (warp >> 1) * 16;
    const int wn = (warp & 1) * 64;
    // ldmatrix lane offsets within a stage (words)
    const uint32_t a_off = (uint32_t)((wm + (l8 & 1) * 8 + r8) * PW + (l8 >> 1) * 4);
    const uint32_t b_off = (uint32_t)(ASTG_W + ((l8 >> 1) * 8 + r8) * PW + (l8 & 1) * 4);

    // One 64x128 GEMM tile: y = x @ W^T + bias, results into smem (fp16).
    auto gemm_tile = [&](int ntg) {
        __syncthreads();   // stage slot 0 free (prev tile / prev phase done)

        auto stage_issue = [&](int c) {
            const uint32_t sbase = smem_base + (uint32_t)(STG_OFF + (c % 3) * 3840) * 4u;
            const int kel = c * 32;
#pragma unroll
            for (int q = 0; q < 3; q++) {
                const int idx = q * 256 + tid;
                if (idx < 256) {               // A: 64 rows x 4 segs
                    const int row = idx >> 2, seg = idx & 3;
                    cp_async16(sbase + (uint32_t)(row * PW + seg * 4) * 4u,
                               g_xh + (size_t)(bw * 64 + row) * 512 + kel + seg * 8);
                } else {                       // B: 128 rows x 4 segs
                    const int bidx = idx - 256;
                    const int row = bidx >> 2, seg = bidx & 3;
                    cp_async16(sbase + (uint32_t)(ASTG_W + row * PW + seg * 4) * 4u,
                               g_wh + (size_t)(ntg * 128 + row) * 512 + kel + seg * 8);
                }
            }
            cp_commit();
        };

        float acc[8][4];
#pragma unroll
        for (int j = 0; j < 8; j++)
#pragma unroll
            for (int c = 0; c < 4; c++) acc[j][c] = 0.f;

        stage_issue(0); stage_issue(1);

        for (int c = 0; c < 16; c++) {
            if (c < 15) cp_wait<1>(); else cp_wait<0>();
            __syncthreads();
            if (c + 2 < 16) stage_issue(c + 2);

            const uint32_t so = smem_base + (uint32_t)(STG_OFF + (c % 3) * 3840) * 4u;
#pragma unroll
            for (int step = 0; step < 2; step++) {
                uint32_t a[4];
                ldm_x4(a, so + (a_off + (uint32_t)(step * 8)) * 4u);
#pragma unroll
                for (int jj = 0; jj < 4; jj++) {
                    uint32_t b[4];
                    ldm_x4(b, so + (b_off + (uint32_t)(wn + jj * 16) * PW
                                    + (uint32_t)(step * 8)) * 4u);
                    mma_f16(acc[2 * jj    ], a, b[0], b[1]);
                    mma_f16(acc[2 * jj + 1], a, b[2], b[3]);
                }
            }
        }

        // Epilogue: +bias, pack fp16, store into kv_s / q_s.
        const int t0 = wm + g, t1 = wm + g + 8;
#pragma unroll
        for (int j = 0; j < 8; j++) {
            const int colg = ntg * 128 + wn + j * 8 + tig * 2;
            const float b0 = bias_s[colg], b1 = bias_s[colg + 1];
            const int mat = colg >> 9;            // 0=Q,1=K,2=V
            const int cin = colg & 511;
            const int h = cin >> 6, d = cin & 63;
            uint32_t base;
            if (mat == 0) base = Q_OFF  + (uint32_t)((h & 1) * 64) * APITCH + (uint32_t)(d >> 1);
            else          base = KV_OFF + (uint32_t)(((mat - 1) * 8 + h) * 64) * APITCH
                                 + (uint32_t)(d >> 1);
            sm[base + t0 * APITCH] = pack2(acc[j][0] + b0, acc[j][1] + b1);
            sm[base + t1 * APITCH] = pack2(acc[j][2] + b0, acc[j][3] + b1);
        }
    };

    // ---- Phase 1a: K (ntg 4..7) and V (ntg 8..11) ----
    for (int ntg = 4; ntg < 12; ntg++) gemm_tile(ntg);

    // ---- Per head-pair: Q tile then attention ----
    const uint32_t aq_base_off = (uint32_t)(((l8 & 1) * 8 + r8) * APITCH + (l8 >> 1) * 4);
    const uint32_t bk_off = (uint32_t)(((l8 >> 1) * 8 + r8) * APITCH + (l8 & 1) * 4);
    const uint32_t bv_off = (uint32_t)(((l8 & 1) * 8 + r8) * APITCH + (l8 >> 1) * 4);

    for (int hp = 0; hp < 4; hp++) {
        gemm_tile(hp);        // Q cols [hp*128, hp*128+128) -> q_s slots 0,1
        __syncthreads();      // Q/K/V ready for attention reads

        const int hw = warp >> 2;           // head slot within pair
        const int h  = hp * 2 + hw;         // global head
        const int qr = (warp & 3) * 16;     // this warp's q rows

        const uint32_t qp_base = smem_base + (uint32_t)(Q_OFF + hw * 64 * APITCH) * 4u;
        const uint32_t k_base  = smem_base + (uint32_t)(KV_OFF + h * 64 * APITCH) * 4u;
        const uint32_t v_base  = smem_base + (uint32_t)(KV_OFF + (8 + h) * 64 * APITCH) * 4u;
        const uint32_t aq_off  = aq_base_off + (uint32_t)(qr * APITCH);
        uint32_t* qp_w = sm + Q_OFF + hw * 64 * APITCH;

        // ---- S = Q K^T ----
        float s[8][4];
#pragma unroll
        for (int j = 0; j < 8; j++)
#pragma unroll
            for (int c = 0; c < 4; c++) s[j][c] = 0.f;

#pragma unroll
        for (int kk = 0; kk < 4; kk++) {
            uint32_t a[4];
            ldm_x4(a, qp_base + (aq_off + (uint32_t)(kk * 8)) * 4u);
#pragma unroll
            for (int jj = 0; jj < 4; jj++) {
                uint32_t b[4];
                ldm_x4(b, k_base + (bk_off + (uint32_t)(jj * 16 * APITCH + kk * 8)) * 4u);
                mma_f16(s[2 * jj    ], a, b[0], b[1]);
                mma_f16(s[2 * jj + 1], a, b[2], b[3]);
            }
        }

        // ---- scale + bias + softmax ----
        const float scale = 0.125f;
        float mx0 = -1e30f, mx1 = -1e30f;
#pragma unroll
        for (int j = 0; j < 8; j++) {
            float2 b0 = *(const float2*)&Bbias[(qr + g    ) * 64 + j * 8 + tig * 2];
            float2 b1 = *(const float2*)&Bbias[(qr + g + 8) * 64 + j * 8 + tig * 2];
            s[j][0] = s[j][0] * scale + b0.x;
            s[j][1] = s[j][1] * scale + b0.y;
            s[j][2] = s[j][2] * scale + b1.x;
            s[j][3] = s[j][3] * scale + b1.y;
            mx0 = fmaxf(mx0, fmaxf(s[j][0], s[j][1]));
            mx1 = fmaxf(mx1, fmaxf(s[j][2], s[j][3]));
        }
        mx0 = fmaxf(mx0, __shfl_xor_sync(0xffffffffu, mx0, 1));
        mx0 = fmaxf(mx0, __shfl_xor_sync(0xffffffffu, mx0, 2));
        mx1 = fmaxf(mx1, __shfl_xor_sync(0xffffffffu, mx1, 1));
        mx1 = fmaxf(mx1, __shfl_xor_sync(0xffffffffu, mx1, 2));

        float sum0 = 0.f, sum1 = 0.f;
#pragma unroll
        for (int j = 0; j < 8; j++) {
            s[j][0] = __expf(s[j][0] - mx0);
            s[j][1] = __expf(s[j][1] - mx0);
            s[j][2] = __expf(s[j][2] - mx1);
            s[j][3] = __expf(s[j][3] - mx1);
            sum0 += s[j][0] + s[j][1];
            sum1 += s[j][2] + s[j][3];
        }
        sum0 += __shfl_xor_sync(0xffffffffu, sum0, 1);
        sum0 += __shfl_xor_sync(0xffffffffu, sum0, 2);
        sum1 += __shfl_xor_sync(0xffffffffu, sum1, 1);
        sum1 += __shfl_xor_sync(0xffffffffu, sum1, 2);
        const float inv0 = 1.0f / sum0, inv1 = 1.0f / sum1;

        // ---- P (fp16) over Q smem (warp-private rows) ----
        __syncwarp();
#pragma unroll
        for (int j = 0; j < 8; j++) {
            qp_w[(qr + g    ) * APITCH + j * 4 + tig] = pack2(s[j][0] * inv0, s[j][1] * inv0);
            qp_w[(qr + g + 8) * APITCH + j * 4 + tig] = pack2(s[j][2] * inv1, s[j][3] * inv1);
        }
        __syncwarp();

        // ---- O = P V ----
        float o[8][4];
#pragma unroll
        for (int j = 0; j < 8; j++)
#pragma unroll
            for (int c = 0; c < 4; c++) o[j][c] = 0.f;

#pragma unroll
        for (int kk = 0; kk < 4; kk++) {
            uint32_t a[4];
            ldm_x4(a, qp_base + (aq_off + (uint32_t)(kk * 8)) * 4u);
#pragma unroll
            for (int jj = 0; jj < 4; jj++) {
                uint32_t b[4];
                ldm_x4_trans(b, v_base + (bv_off + (uint32_t)(kk * 16 * APITCH + jj * 8)) * 4u);
                mma_f16(o[2 * jj    ], a, b[0], b[1]);
                mma_f16(o[2 * jj + 1], a, b[2], b[3]);
            }
        }

        // ---- output: flat[((bw*64 + t) * 512) + h*64 + d], fp32 ----
        float* o0 = out + ((size_t)bw * 64 + qr + g) * 512 + h * 64;
        float* o1 = o0 + 8 * 512;
#pragma unroll
        for (int j = 0; j < 8; j++) {
            *(float2*)&o0[j * 8 + tig * 2] = make_float2(o[j][0], o[j][1]);
            *(float2*)&o1[j * 8 + tig * 2] = make_float2(o[j][2], o[j][3]);
        }
        __syncthreads();      // q_s reusable next hp
    }
}

// ---------------------------------------------------------------------------
extern "C" void kernel_launch(void* const* d_in, const int* in_sizes, int n_in,
                              void* d_out, int out_size)
{
    const float* x  = (const float*)d_in[0];
    const float* Wq = (const float*)d_in[1];
    const float* bq = (const float*)d_in[2];
    const float* Wk = (const float*)d_in[3];
    const float* bk = (const float*)d_in[4];
    const float* Wv = (const float*)d_in[5];
    const float* bv = (const float*)d_in[6];
    const float* Bb = (const float*)d_in[7];
    float* out = (float*)d_out;

    cudaFuncSetAttribute(fused_kernel, cudaFuncAttributeMaxDynamicSharedMemorySize,
                         FUSED_SMEM);

    conv_x_kernel<<<8192, 256>>>(x);
    conv_w_kernel<<<384, 256>>>(Wq, Wk, Wv);

    fused_kernel<<<512, 256, FUSED_SMEM>>>(bq, bk, bv, Bb, out);
}

// round 14
// speedup vs baseline: 1.2636x; 1.2636x over previous
#include <cuda_runtime.h>
#include <cuda_fp16.h>
#include <cstdint>

#define QKV_SZ (512u * 8u * 64u * 64u)   // halfs per matrix
__device__ __align__(16) __half g_qkv[3 * QKV_SZ];   // fp16 [which][bw][h][t][d]
__device__ __align__(16) __half g_xh[32768u * 512u]; // x as fp16
__device__ __align__(16) __half g_wh[1536u * 512u];  // Wq|Wk|Wv as fp16

__device__ __forceinline__ uint32_t pack2(float a, float b) {
    __half2 h = __halves2half2(__float2half_rn(a), __float2half_rn(b));
    return *(uint32_t*)&h;
}

__device__ __forceinline__ void mma_f16(float c[4], const uint32_t a[4],
                                        uint32_t b0, uint32_t b1) {
    asm volatile(
        "mma.sync.aligned.m16n8k16.row.col.f32.f16.f16.f32 "
        "{%0,%1,%2,%3}, {%4,%5,%6,%7}, {%8,%9}, {%0,%1,%2,%3};"
        : "+f"(c[0]), "+f"(c[1]), "+f"(c[2]), "+f"(c[3])
        : "r"(a[0]), "r"(a[1]), "r"(a[2]), "r"(a[3]), "r"(b0), "r"(b1));
}

__device__ __forceinline__ void ldm_x4(uint32_t* r, uint32_t addr) {
    asm volatile("ldmatrix.sync.aligned.m8n8.x4.shared.b16 {%0,%1,%2,%3}, [%4];"
                 : "=r"(r[0]), "=r"(r[1]), "=r"(r[2]), "=r"(r[3]) : "r"(addr));
}
__device__ __forceinline__ void ldm_x4_trans(uint32_t* r, uint32_t addr) {
    asm volatile("ldmatrix.sync.aligned.m8n8.x4.trans.shared.b16 {%0,%1,%2,%3}, [%4];"
                 : "=r"(r[0]), "=r"(r[1]), "=r"(r[2]), "=r"(r[3]) : "r"(addr));
}

__device__ __forceinline__ void cp_async16(uint32_t smem_addr, const void* gptr) {
    asm volatile("cp.async.cg.shared.global [%0], [%1], 16;\n" :: "r"(smem_addr), "l"(gptr));
}
__device__ __forceinline__ void cp_commit() { asm volatile("cp.async.commit_group;"); }
template <int N> __device__ __forceinline__ void cp_wait() {
    asm volatile("cp.async.wait_group %0;" :: "n"(N));
}

// ---------------------------------------------------------------------------
// Pre-convert: fp32 -> fp16(RN). 8 floats per thread.
// ---------------------------------------------------------------------------
__global__ void __launch_bounds__(256) conv_x_kernel(const float* __restrict__ x)
{
    const int i = blockIdx.x * 256 + threadIdx.x;
    float4 v0 = ((const float4*)x)[2 * i];
    float4 v1 = ((const float4*)x)[2 * i + 1];
    uint4 u;
    u.x = pack2(v0.x, v0.y); u.y = pack2(v0.z, v0.w);
    u.z = pack2(v1.x, v1.y); u.w = pack2(v1.z, v1.w);
    ((uint4*)g_xh)[i] = u;
}

__global__ void __launch_bounds__(256) conv_w_kernel(
    const float* __restrict__ Wq, const float* __restrict__ Wk, const float* __restrict__ Wv)
{
    const int i = blockIdx.x * 256 + threadIdx.x;
    const int which = i >> 15;
    const int sub = i & 32767;
    const float* W = (which == 0) ? Wq : (which == 1) ? Wk : Wv;
    float4 v0 = ((const float4*)W)[2 * sub];
    float4 v1 = ((const float4*)W)[2 * sub + 1];
    uint4 u;
    u.x = pack2(v0.x, v0.y); u.y = pack2(v0.z, v0.w);
    u.z = pack2(v1.x, v1.y); u.w = pack2(v1.z, v1.w);
    ((uint4*)g_wh)[i] = u;
}

// ---------------------------------------------------------------------------
// Kernel A: QKV projection, fp16 m16n8k16, 2 CTAs/SM.
// CTA tile 128x128, 256 threads, 8 warps (2x4 grid of 64x32 warp tiles).
// K chunk 32, 4-stage cp.async pipeline. ldmatrix.x4 operand delivery,
// all 6 ldm of a k16 step issued before its mma block (overlap freedom).
// Grid (12, 256): blockIdx.x = N-tile (fast) -> x L2 reuse.
// ---------------------------------------------------------------------------
#define KC 32
#define PW 20                            // words per staged row (16 data + 4 pad)
#define STAGE_W (256 * PW)               // 128 A rows + 128 B rows = 5120 words
#define NSTAGE 4
#define PROJ_SMEM (NSTAGE * STAGE_W * 4) // 81920 B -> 2 CTAs/SM

__global__ void __launch_bounds__(256, 2) qkv_proj_kernel(
    const float* __restrict__ bq, const float* __restrict__ bk, const float* __restrict__ bv)
{
    extern __shared__ uint32_t sm[];

    const int tid  = threadIdx.x;
    const int warp = tid >> 5, lane = tid & 31;
    const int g = lane >> 2, tig = lane & 3;
    const int l8 = lane >> 3, r8 = lane & 7;
    const int wm = (warp >> 2) * 64;     // 2 row-groups
    const int wn = (warp & 3) * 32;      // 4 col-groups

    const int nb = blockIdx.x * 128;
    const int mb = blockIdx.y * 128;
    const int which = nb >> 9;
    const int nw0 = nb & 511;
    const float* __restrict__ bias = (which == 0) ? bq : (which == 1) ? bk : bv;
    __half* __restrict__ dst = g_qkv + (size_t)which * QKV_SZ;

    const uint32_t smem_base = (uint32_t)__cvta_generic_to_shared(sm);

    const uint32_t a_off = (uint32_t)((wm + (l8 & 1) * 8 + r8) * PW + (l8 >> 1) * 4);
    const uint32_t b_off = (uint32_t)((128 + wn + (l8 >> 1) * 8 + r8) * PW + (l8 & 1) * 4);

    float acc[4][4][4];
#pragma unroll
    for (int i = 0; i < 4; i++)
#pragma unroll
        for (int j = 0; j < 4; j++)
#pragma unroll
            for (int c = 0; c < 4; c++) acc[i][j][c] = 0.f;

    auto issue = [&](int c) {
        const uint32_t sbase = smem_base + (uint32_t)((c & 3) * STAGE_W) * 4u;
        const int kel = c * KC;
#pragma unroll
        for (int q = 0; q < 4; q++) {
            const int idx = q * 256 + tid;
            if (idx < 512) {             // A
                const int row = idx >> 2, i = idx & 3;
                cp_async16(sbase + (uint32_t)(row * PW + i * 4) * 4u,
                           g_xh + (size_t)(mb + row) * 512 + kel + i * 8);
            } else {                     // B
                const int bidx = idx - 512;
                const int row = bidx >> 2, i = bidx & 3;
                cp_async16(sbase + (uint32_t)((128 + row) * PW + i * 4) * 4u,
                           g_wh + (size_t)(nb + row) * 512 + kel + i * 8);
            }
        }
        cp_commit();
    };

    issue(0); issue(1); issue(2);

    for (int c = 0; c < 16; c++) {
        if (c <= 13) cp_wait<2>();
        else if (c == 14) cp_wait<1>();
        else cp_wait<0>();
        __syncthreads();
        if (c + 3 < 16) issue(c + 3);

        const uint32_t stage_addr = smem_base + (uint32_t)((c & 3) * STAGE_W) * 4u;

#pragma unroll
        for (int step = 0; step < 2; step++) {
            const uint32_t so = stage_addr + (uint32_t)(step * 8) * 4u;
            uint32_t a[4][4], b[2][4];
#pragma unroll
            for (int i = 0; i < 4; i++)
                ldm_x4(a[i], so + (a_off + (uint32_t)(i * 16 * PW)) * 4u);
#pragma unroll
            for (int jj = 0; jj < 2; jj++)
                ldm_x4(b[jj], so + (b_off + (uint32_t)(jj * 16 * PW)) * 4u);
#pragma unroll
            for (int jj = 0; jj < 2; jj++)
#pragma unroll
                for (int i = 0; i < 4; i++) {
                    mma_f16(acc[i][2 * jj    ], a[i], b[jj][0], b[jj][1]);
                    mma_f16(acc[i][2 * jj + 1], a[i], b[jj][2], b[jj][3]);
                }
        }
    }

    // Epilogue: +bias fp32, pack half2, scatter [bw][h][t][d].
#pragma unroll
    for (int i = 0; i < 4; i++) {
        const int m0 = mb + wm + i * 16 + g;
#pragma unroll
        for (int j = 0; j < 4; j++) {
            const int col = nw0 + wn + j * 8 + tig * 2;
            const float bv0 = bias[col], bv1 = bias[col + 1];
            const int h = col >> 6, d = col & 63;
            {
                const int m = m0;
                size_t o = (((size_t)(m >> 6) * 8 + h) * 64 + (m & 63)) * 64 + d;
                *(uint32_t*)&dst[o] = pack2(acc[i][j][0] + bv0, acc[i][j][1] + bv1);
            }
            {
                const int m = m0 + 8;
                size_t o = (((size_t)(m >> 6) * 8 + h) * 64 + (m & 63)) * 64 + d;
                *(uint32_t*)&dst[o] = pack2(acc[i][j][2] + bv0, acc[i][j][3] + bv1);
            }
        }
    }
}

// ---------------------------------------------------------------------------
// Kernel B: per-(window, head) attention, fp16 mma + ldmatrix.x4.
// 4096 CTAs x 128 threads. Q/K/V loaded via cp.async (12 x 16B per thread,
// all in flight at once) -> high MLP, DRAM-bandwidth-bound path.
// ---------------------------------------------------------------------------
#define APITCH 36

__global__ void __launch_bounds__(128) attn_kernel(
    const float* __restrict__ Bbias, float* __restrict__ out)
{
    __shared__ uint32_t qp_s[64 * APITCH];   // Q, later P (warp-private rows)
    __shared__ uint32_t k_s [64 * APITCH];
    __shared__ uint32_t v_s [64 * APITCH];   // [t][d] row-major

    const int tid  = threadIdx.x;
    const int warp = tid >> 5, lane = tid & 31;
    const int g = lane >> 2, tig = lane & 3;
    const int l8 = lane >> 3, r8 = lane & 7;
    const int wh = blockIdx.x;
    const int h  = wh & 7;
    const int bw = wh >> 3;
    const size_t base = (size_t)wh * 4096;

    const __half* qg = g_qkv + base;
    const __half* kg = g_qkv + QKV_SZ + base;
    const __half* vg = g_qkv + 2u * QKV_SZ + base;

    const uint32_t qp_base = (uint32_t)__cvta_generic_to_shared(qp_s);
    const uint32_t k_base  = (uint32_t)__cvta_generic_to_shared(k_s);
    const uint32_t v_base  = (uint32_t)__cvta_generic_to_shared(v_s);

    // 512 16B-chunks per tensor, 4/thread each; all 12 cp.async outstanding.
#pragma unroll
    for (int i = 0; i < 4; i++) {
        const int c = i * 128 + tid;
        const int t = c >> 3, w4 = (c & 7) * 4;
        const uint32_t soff = (uint32_t)(t * APITCH + w4) * 4u;
        cp_async16(qp_base + soff, qg + c * 8);
        cp_async16(k_base  + soff, kg + c * 8);
        cp_async16(v_base  + soff, vg + c * 8);
    }
    cp_commit();
    cp_wait<0>();
    __syncthreads();

    const int qr = warp * 16;

    const uint32_t aq_off = (uint32_t)((qr + (l8 & 1) * 8 + r8) * APITCH + (l8 >> 1) * 4);
    const uint32_t bk_off = (uint32_t)(((l8 >> 1) * 8 + r8) * APITCH + (l8 & 1) * 4);
    const uint32_t bv_off = (uint32_t)(((l8 & 1) * 8 + r8) * APITCH + (l8 >> 1) * 4);

    // ---- S = Q K^T ----
    float s[8][4];
#pragma unroll
    for (int j = 0; j < 8; j++)
#pragma unroll
        for (int c = 0; c < 4; c++) s[j][c] = 0.f;

#pragma unroll
    for (int kk = 0; kk < 4; kk++) {
        uint32_t a[4];
        ldm_x4(a, qp_base + (aq_off + (uint32_t)(kk * 8)) * 4u);
#pragma unroll
        for (int jj = 0; jj < 4; jj++) {
            uint32_t b[4];
            ldm_x4(b, k_base + (bk_off + (uint32_t)(jj * 16 * APITCH + kk * 8)) * 4u);
            mma_f16(s[2 * jj    ], a, b[0], b[1]);
            mma_f16(s[2 * jj + 1], a, b[2], b[3]);
        }
    }

    // ---- scale + bias + softmax ----
    const float scale = 0.125f;
    float mx0 = -1e30f, mx1 = -1e30f;
#pragma unroll
    for (int j = 0; j < 8; j++) {
        float2 b0 = *(const float2*)&Bbias[(qr + g    ) * 64 + j * 8 + tig * 2];
        float2 b1 = *(const float2*)&Bbias[(qr + g + 8) * 64 + j * 8 + tig * 2];
        s[j][0] = s[j][0] * scale + b0.x;
        s[j][1] = s[j][1] * scale + b0.y;
        s[j][2] = s[j][2] * scale + b1.x;
        s[j][3] = s[j][3] * scale + b1.y;
        mx0 = fmaxf(mx0, fmaxf(s[j][0], s[j][1]));
        mx1 = fmaxf(mx1, fmaxf(s[j][2], s[j][3]));
    }
    mx0 = fmaxf(mx0, __shfl_xor_sync(0xffffffffu, mx0, 1));
    mx0 = fmaxf(mx0, __shfl_xor_sync(0xffffffffu, mx0, 2));
    mx1 = fmaxf(mx1, __shfl_xor_sync(0xffffffffu, mx1, 1));
    mx1 = fmaxf(mx1, __shfl_xor_sync(0xffffffffu, mx1, 2));

    float sum0 = 0.f, sum1 = 0.f;
#pragma unroll
    for (int j = 0; j < 8; j++) {
        s[j][0] = __expf(s[j][0] - mx0);
        s[j][1] = __expf(s[j][1] - mx0);
        s[j][2] = __expf(s[j][2] - mx1);
        s[j][3] = __expf(s[j][3] - mx1);
        sum0 += s[j][0] + s[j][1];
        sum1 += s[j][2] + s[j][3];
    }
    sum0 += __shfl_xor_sync(0xffffffffu, sum0, 1);
    sum0 += __shfl_xor_sync(0xffffffffu, sum0, 2);
    sum1 += __shfl_xor_sync(0xffffffffu, sum1, 1);
    sum1 += __shfl_xor_sync(0xffffffffu, sum1, 2);
    const float inv0 = 1.0f / sum0, inv1 = 1.0f / sum1;

    // ---- P (fp16) over Q smem ----
    __syncwarp();
#pragma unroll
    for (int j = 0; j < 8; j++) {
        qp_s[(qr + g    ) * APITCH + j * 4 + tig] = pack2(s[j][0] * inv0, s[j][1] * inv0);
        qp_s[(qr + g + 8) * APITCH + j * 4 + tig] = pack2(s[j][2] * inv1, s[j][3] * inv1);
    }
    __syncwarp();

    // ---- O = P V ----
    float o[8][4];
#pragma unroll
    for (int j = 0; j < 8; j++)
#pragma unroll
        for (int c = 0; c < 4; c++) o[j][c] = 0.f;

#pragma unroll
    for (int kk = 0; kk < 4; kk++) {
        uint32_t a[4];
        ldm_x4(a, qp_base + (aq_off + (uint32_t)(kk * 8)) * 4u);
#pragma unroll
        for (int jj = 0; jj < 4; jj++) {
            uint32_t b[4];
            ldm_x4_trans(b, v_base + (bv_off + (uint32_t)(kk * 16 * APITCH + jj * 8)) * 4u);
            mma_f16(o[2 * jj    ], a, b[0], b[1]);
            mma_f16(o[2 * jj + 1], a, b[2], b[3]);
        }
    }

    // ---- output ----
    float* o0 = out + ((size_t)bw * 64 + qr + g) * 512 + h * 64;
    float* o1 = o0 + 8 * 512;
#pragma unroll
    for (int j = 0; j < 8; j++) {
        *(float2*)&o0[j * 8 + tig * 2] = make_float2(o[j][0], o[j][1]);
        *(float2*)&o1[j * 8 + tig * 2] = make_float2(o[j][2], o[j][3]);
    }
}

// ---------------------------------------------------------------------------
extern "C" void kernel_launch(void* const* d_in, const int* in_sizes, int n_in,
                              void* d_out, int out_size)
{
    const float* x  = (const float*)d_in[0];
    const float* Wq = (const float*)d_in[1];
    const float* bq = (const float*)d_in[2];
    const float* Wk = (const float*)d_in[3];
    const float* bk = (const float*)d_in[4];
    const float* Wv = (const float*)d_in[5];
    const float* bv = (const float*)d_in[6];
    const float* Bb = (const float*)d_in[7];
    float* out = (float*)d_out;

    cudaFuncSetAttribute(qkv_proj_kernel, cudaFuncAttributeMaxDynamicSharedMemorySize,
                         PROJ_SMEM);

    conv_x_kernel<<<8192, 256>>>(x);
    conv_w_kernel<<<384, 256>>>(Wq, Wk, Wv);

    dim3 gA(12, 256);
    qkv_proj_kernel<<<gA, 256, PROJ_SMEM>>>(bq, bk, bv);

    attn_kernel<<<4096, 128>>>(Bb, out);
}